// round 2
// baseline (speedup 1.0000x reference)
#include <cuda_runtime.h>
#include <cstdint>

#define D_MODEL 1280
#define SEQ     1024
#define N_BF    8
#define N_FR    4
#define N_HEADS 20
#define HDIM    64
#define M_TOT   (N_BF*SEQ)   // 8192

// Scratch (allocation-free rule: device globals)
__device__ float g_q[(size_t)M_TOT * D_MODEL];
__device__ float g_k[(size_t)M_TOT * D_MODEL];
__device__ float g_v[(size_t)M_TOT * D_MODEL];
__device__ float g_attn[(size_t)M_TOT * D_MODEL];

__device__ __forceinline__ float f2tf(float x) {
    uint32_t u;
    asm("cvt.rna.tf32.f32 %0, %1;" : "=r"(u) : "f"(x));
    return __uint_as_float(u);
}

__device__ __forceinline__ void mma_m16n8k8(float d[4], const float a[4], const float b[2]) {
    asm volatile(
        "mma.sync.aligned.m16n8k8.row.col.f32.tf32.tf32.f32 "
        "{%0,%1,%2,%3}, {%4,%5,%6,%7}, {%8,%9}, {%0,%1,%2,%3};\n"
        : "+f"(d[0]), "+f"(d[1]), "+f"(d[2]), "+f"(d[3])
        : "r"(__float_as_uint(a[0])), "r"(__float_as_uint(a[1])),
          "r"(__float_as_uint(a[2])), "r"(__float_as_uint(a[3])),
          "r"(__float_as_uint(b[0])), "r"(__float_as_uint(b[1])));
}

// ---------------------------------------------------------------------------
// C[M,N] = A[M,K] @ W[K,N] + bias (+ optional residual). tf32 mma, 128x128x32.
// ---------------------------------------------------------------------------
template<bool ADD_RES>
__global__ __launch_bounds__(256, 2)
void gemm_bias_kernel(const float* __restrict__ A, const float* __restrict__ W,
                      const float* __restrict__ bias, const float* __restrict__ res,
                      float* __restrict__ C, int M, int N, int K)
{
    __shared__ float As[128][33];
    __shared__ float Bs[128][33];   // Bs[n][k]

    const int bm = blockIdx.y, bn = blockIdx.x;
    const int tid = threadIdx.x;
    const int warp = tid >> 5, lane = tid & 31;
    const int wm = warp >> 2, wn = warp & 3;         // 2x4 warp grid, each 64x32
    const int gid = lane >> 2, tig = lane & 3;

    float acc[4][4][4];
    #pragma unroll
    for (int mt = 0; mt < 4; mt++)
        #pragma unroll
        for (int nt = 0; nt < 4; nt++)
            #pragma unroll
            for (int i = 0; i < 4; i++) acc[mt][nt][i] = 0.f;

    const float* Ab = A + (size_t)bm * 128 * K;
    const float* Wb = W + bn * 128;

    for (int kt = 0; kt < K; kt += 32) {
        #pragma unroll
        for (int i = 0; i < 4; i++) {
            int idx = tid + i * 256;
            int r = idx >> 3, c = (idx & 7) * 4;
            float4 v = *reinterpret_cast<const float4*>(Ab + (size_t)r * K + kt + c);
            As[r][c + 0] = f2tf(v.x); As[r][c + 1] = f2tf(v.y);
            As[r][c + 2] = f2tf(v.z); As[r][c + 3] = f2tf(v.w);
        }
        #pragma unroll
        for (int i = 0; i < 4; i++) {
            int idx = tid + i * 256;
            int r = idx >> 5, c = (idx & 31) * 4;
            float4 v = *reinterpret_cast<const float4*>(Wb + (size_t)(kt + r) * N + c);
            Bs[c + 0][r] = f2tf(v.x); Bs[c + 1][r] = f2tf(v.y);
            Bs[c + 2][r] = f2tf(v.z); Bs[c + 3][r] = f2tf(v.w);
        }
        __syncthreads();

        #pragma unroll
        for (int kk = 0; kk < 32; kk += 8) {
            float af[4][4], bfr[4][2];
            #pragma unroll
            for (int mt = 0; mt < 4; mt++) {
                int r = wm * 64 + mt * 16 + gid;
                af[mt][0] = As[r][kk + tig];     af[mt][1] = As[r + 8][kk + tig];
                af[mt][2] = As[r][kk + tig + 4]; af[mt][3] = As[r + 8][kk + tig + 4];
            }
            #pragma unroll
            for (int nt = 0; nt < 4; nt++) {
                int cc = wn * 32 + nt * 8 + gid;
                bfr[nt][0] = Bs[cc][kk + tig];
                bfr[nt][1] = Bs[cc][kk + tig + 4];
            }
            #pragma unroll
            for (int mt = 0; mt < 4; mt++)
                #pragma unroll
                for (int nt = 0; nt < 4; nt++)
                    mma_m16n8k8(acc[mt][nt], af[mt], bfr[nt]);
        }
        __syncthreads();
    }

    #pragma unroll
    for (int mt = 0; mt < 4; mt++) {
        int row = bm * 128 + wm * 64 + mt * 16 + gid;
        #pragma unroll
        for (int nt = 0; nt < 4; nt++) {
            int col = bn * 128 + wn * 32 + nt * 8 + 2 * tig;
            float b0 = bias[col], b1 = bias[col + 1];
            size_t i0 = (size_t)row * N + col;
            size_t i1 = i0 + 8 * (size_t)N;
            float v0 = acc[mt][nt][0] + b0, v1 = acc[mt][nt][1] + b1;
            float v2 = acc[mt][nt][2] + b0, v3 = acc[mt][nt][3] + b1;
            if (ADD_RES) { v0 += res[i0]; v1 += res[i0 + 1]; v2 += res[i1]; v3 += res[i1 + 1]; }
            C[i0] = v0; C[i0 + 1] = v1; C[i1] = v2; C[i1 + 1] = v3;
        }
    }
}

// ---------------------------------------------------------------------------
// Flash attention over 2S keys. Block = (qtile 64 rows, head, bf). 4 warps.
// First 16 key-tiles come from frame 0 of the same batch group (mode 'first').
// ---------------------------------------------------------------------------
__global__ __launch_bounds__(128)
void attn_kernel()
{
    extern __shared__ float smbuf[];
    float (*Qs)[68] = reinterpret_cast<float(*)[68]>(smbuf);
    float (*Ks)[68] = reinterpret_cast<float(*)[68]>(smbuf + 64 * 68);
    float (*Vs)[68] = reinterpret_cast<float(*)[68]>(smbuf + 2 * 64 * 68);
    float (*Ps)[68] = reinterpret_cast<float(*)[68]>(smbuf + 3 * 64 * 68);

    const int qt = blockIdx.x, h = blockIdx.y, bfi = blockIdx.z;
    const int bf0 = bfi & ~(N_FR - 1);
    const int tid = threadIdx.x;
    const int w = tid >> 5, lane = tid & 31;
    const int gid = lane >> 2, tig = lane & 3;
    const float scale = 0.125f;   // 1/sqrt(64)

    // Load Q tile (pre-scaled)
    #pragma unroll
    for (int i = 0; i < 8; i++) {
        int idx = tid + i * 128;
        int r = idx >> 4, c = (idx & 15) * 4;
        const float* p = g_q + ((size_t)(bfi * SEQ + qt * 64 + r)) * D_MODEL + h * HDIM + c;
        float4 v = *reinterpret_cast<const float4*>(p);
        Qs[r][c + 0] = f2tf(v.x * scale); Qs[r][c + 1] = f2tf(v.y * scale);
        Qs[r][c + 2] = f2tf(v.z * scale); Qs[r][c + 3] = f2tf(v.w * scale);
    }

    float oacc[8][4];
    #pragma unroll
    for (int nt = 0; nt < 8; nt++)
        #pragma unroll
        for (int i = 0; i < 4; i++) oacc[nt][i] = 0.f;
    float m0 = -3e38f, m1 = -3e38f, l0 = 0.f, l1 = 0.f;

    const int rW = w * 16 + gid;   // this thread's first row within the 64-row q tile

    for (int t = 0; t < 32; t++) {
        const int sbf = (t < 16) ? bf0 : bfi;
        const int k0 = (t & 15) * 64;

        #pragma unroll
        for (int i = 0; i < 8; i++) {
            int idx = tid + i * 128;
            int r = idx >> 4, c = (idx & 15) * 4;
            size_t base = ((size_t)(sbf * SEQ + k0 + r)) * D_MODEL + h * HDIM + c;
            float4 kv = *reinterpret_cast<const float4*>(g_k + base);
            Ks[r][c + 0] = f2tf(kv.x); Ks[r][c + 1] = f2tf(kv.y);
            Ks[r][c + 2] = f2tf(kv.z); Ks[r][c + 3] = f2tf(kv.w);
            float4 vv = *reinterpret_cast<const float4*>(g_v + base);
            Vs[r][c + 0] = f2tf(vv.x); Vs[r][c + 1] = f2tf(vv.y);
            Vs[r][c + 2] = f2tf(vv.z); Vs[r][c + 3] = f2tf(vv.w);
        }
        __syncthreads();

        // S = (Q*scale) @ K^T   — 16x64 per warp
        float sacc[8][4];
        #pragma unroll
        for (int nt = 0; nt < 8; nt++)
            #pragma unroll
            for (int i = 0; i < 4; i++) sacc[nt][i] = 0.f;

        #pragma unroll
        for (int kk = 0; kk < 64; kk += 8) {
            float aq[4];
            aq[0] = Qs[rW][kk + tig];     aq[1] = Qs[rW + 8][kk + tig];
            aq[2] = Qs[rW][kk + tig + 4]; aq[3] = Qs[rW + 8][kk + tig + 4];
            #pragma unroll
            for (int nt = 0; nt < 8; nt++) {
                float bk[2];
                bk[0] = Ks[nt * 8 + gid][kk + tig];
                bk[1] = Ks[nt * 8 + gid][kk + tig + 4];
                mma_m16n8k8(sacc[nt], aq, bk);
            }
        }

        // Online softmax (rows rW and rW+8)
        float mx0 = -3e38f, mx1 = -3e38f;
        #pragma unroll
        for (int nt = 0; nt < 8; nt++) {
            mx0 = fmaxf(mx0, fmaxf(sacc[nt][0], sacc[nt][1]));
            mx1 = fmaxf(mx1, fmaxf(sacc[nt][2], sacc[nt][3]));
        }
        mx0 = fmaxf(mx0, __shfl_xor_sync(0xffffffffu, mx0, 1));
        mx0 = fmaxf(mx0, __shfl_xor_sync(0xffffffffu, mx0, 2));
        mx1 = fmaxf(mx1, __shfl_xor_sync(0xffffffffu, mx1, 1));
        mx1 = fmaxf(mx1, __shfl_xor_sync(0xffffffffu, mx1, 2));

        float mn0 = fmaxf(m0, mx0), mn1 = fmaxf(m1, mx1);
        float a0 = __expf(m0 - mn0), a1 = __expf(m1 - mn1);
        float s0 = 0.f, s1 = 0.f;
        #pragma unroll
        for (int nt = 0; nt < 8; nt++) {
            float p0 = __expf(sacc[nt][0] - mn0), p1 = __expf(sacc[nt][1] - mn0);
            float p2 = __expf(sacc[nt][2] - mn1), p3 = __expf(sacc[nt][3] - mn1);
            s0 += p0 + p1; s1 += p2 + p3;
            sacc[nt][0] = p0; sacc[nt][1] = p1; sacc[nt][2] = p2; sacc[nt][3] = p3;
        }
        s0 += __shfl_xor_sync(0xffffffffu, s0, 1);
        s0 += __shfl_xor_sync(0xffffffffu, s0, 2);
        s1 += __shfl_xor_sync(0xffffffffu, s1, 1);
        s1 += __shfl_xor_sync(0xffffffffu, s1, 2);
        l0 = l0 * a0 + s0; l1 = l1 * a1 + s1;
        m0 = mn0; m1 = mn1;

        #pragma unroll
        for (int nt = 0; nt < 8; nt++) {
            oacc[nt][0] *= a0; oacc[nt][1] *= a0;
            oacc[nt][2] *= a1; oacc[nt][3] *= a1;
        }

        // Stage P for the PV mma
        #pragma unroll
        for (int nt = 0; nt < 8; nt++) {
            int col = nt * 8 + 2 * tig;
            Ps[rW][col]         = f2tf(sacc[nt][0]);
            Ps[rW][col + 1]     = f2tf(sacc[nt][1]);
            Ps[rW + 8][col]     = f2tf(sacc[nt][2]);
            Ps[rW + 8][col + 1] = f2tf(sacc[nt][3]);
        }
        __syncthreads();

        // O += P @ V
        #pragma unroll
        for (int kk = 0; kk < 64; kk += 8) {
            float ap[4];
            ap[0] = Ps[rW][kk + tig];     ap[1] = Ps[rW + 8][kk + tig];
            ap[2] = Ps[rW][kk + tig + 4]; ap[3] = Ps[rW + 8][kk + tig + 4];
            #pragma unroll
            for (int nt = 0; nt < 8; nt++) {
                float bv[2];
                bv[0] = Vs[kk + tig][nt * 8 + gid];
                bv[1] = Vs[kk + tig + 4][nt * 8 + gid];
                mma_m16n8k8(oacc[nt], ap, bv);
            }
        }
        __syncthreads();
    }

    const float inv0 = 1.f / l0, inv1 = 1.f / l1;
    #pragma unroll
    for (int nt = 0; nt < 8; nt++) {
        int dcol = h * HDIM + nt * 8 + 2 * tig;
        size_t b0 = ((size_t)(bfi * SEQ + qt * 64 + rW)) * D_MODEL + dcol;
        size_t b1 = b0 + 8 * (size_t)D_MODEL;
        g_attn[b0] = oacc[nt][0] * inv0; g_attn[b0 + 1] = oacc[nt][1] * inv0;
        g_attn[b1] = oacc[nt][2] * inv1; g_attn[b1 + 1] = oacc[nt][3] * inv1;
    }
}

// ---------------------------------------------------------------------------

extern "C" void kernel_launch(void* const* d_in, const int* in_sizes, int n_in,
                              void* d_out, int out_size)
{
    const float* hs = (const float*)d_in[0];
    const float* Wq = (const float*)d_in[1];
    const float* Wk = (const float*)d_in[2];
    const float* Wv = (const float*)d_in[3];
    const float* Wo = (const float*)d_in[4];
    const float* bq = (const float*)d_in[5];
    const float* bk = (const float*)d_in[6];
    const float* bv = (const float*)d_in[7];
    const float* bo = (const float*)d_in[8];
    float* out = (float*)d_out;

    float *qp, *kp, *vp, *ap;
    cudaGetSymbolAddress((void**)&qp, g_q);
    cudaGetSymbolAddress((void**)&kp, g_k);
    cudaGetSymbolAddress((void**)&vp, g_v);
    cudaGetSymbolAddress((void**)&ap, g_attn);

    dim3 blk(256), grd(D_MODEL / 128, M_TOT / 128);
    gemm_bias_kernel<false><<<grd, blk>>>(hs, Wq, bq, nullptr, qp, M_TOT, D_MODEL, D_MODEL);
    gemm_bias_kernel<false><<<grd, blk>>>(hs, Wk, bk, nullptr, kp, M_TOT, D_MODEL, D_MODEL);
    gemm_bias_kernel<false><<<grd, blk>>>(hs, Wv, bv, nullptr, vp, M_TOT, D_MODEL, D_MODEL);

    const int attn_smem = 4 * 64 * 68 * 4;   // 69632 B
    cudaFuncSetAttribute((const void*)attn_kernel,
                         cudaFuncAttributeMaxDynamicSharedMemorySize, attn_smem);
    attn_kernel<<<dim3(SEQ / 64, N_HEADS, N_BF), 128, attn_smem>>>();

    gemm_bias_kernel<true><<<grd, blk>>>(ap, Wo, bo, hs, out, M_TOT, D_MODEL, D_MODEL);
}

// round 3
// speedup vs baseline: 1.5600x; 1.5600x over previous
#include <cuda_runtime.h>
#include <cuda_bf16.h>
#include <cstdint>

#define D_MODEL 1280
#define SEQ     1024
#define N_BF    8
#define N_FR    4
#define N_HEADS 20
#define HDIM    64
#define M_TOT   (N_BF*SEQ)   // 8192

// Scratch (allocation-free rule: device globals). All bf16.
__device__ __nv_bfloat16 g_q[(size_t)M_TOT * D_MODEL];
__device__ __nv_bfloat16 g_k[(size_t)M_TOT * D_MODEL];
__device__ __nv_bfloat16 g_v[(size_t)M_TOT * D_MODEL];
__device__ __nv_bfloat16 g_attn[(size_t)M_TOT * D_MODEL];

__device__ __forceinline__ uint32_t packbf(float lo, float hi) {
    __nv_bfloat162 h = __floats2bfloat162_rn(lo, hi);
    return *reinterpret_cast<uint32_t*>(&h);
}

__device__ __forceinline__ void mma_bf16(float d[4], const uint32_t a[4], const uint32_t b[2]) {
    asm volatile(
        "mma.sync.aligned.m16n8k16.row.col.f32.bf16.bf16.f32 "
        "{%0,%1,%2,%3}, {%4,%5,%6,%7}, {%8,%9}, {%0,%1,%2,%3};\n"
        : "+f"(d[0]), "+f"(d[1]), "+f"(d[2]), "+f"(d[3])
        : "r"(a[0]), "r"(a[1]), "r"(a[2]), "r"(a[3]),
          "r"(b[0]), "r"(b[1]));
}

// ---------------------------------------------------------------------------
// C[M,N] = A[M,K] @ W[K,N] + bias (+ residual). bf16 mma, 128x128x32 tiles.
// A may be fp32 (converted on stage) or bf16 (raw copy). C fp32 or bf16.
// ---------------------------------------------------------------------------
template<bool A_BF16, bool OUT_BF16, bool ADD_RES>
__global__ __launch_bounds__(256, 2)
void gemm_kernel(const void* __restrict__ Ap, const float* __restrict__ W,
                 const float* __restrict__ bias, const float* __restrict__ res,
                 void* __restrict__ Cp, int M, int N, int K)
{
    __shared__ __nv_bfloat16 As[128][40];
    __shared__ __nv_bfloat16 Bs[128][40];   // Bs[n][k]

    const int bm = blockIdx.y, bn = blockIdx.x;
    const int tid = threadIdx.x;
    const int warp = tid >> 5, lane = tid & 31;
    const int wm = warp >> 2, wn = warp & 3;     // 2x4 warp grid, each 64x32
    const int gid = lane >> 2, tig = lane & 3;

    float acc[4][4][4];
    #pragma unroll
    for (int mt = 0; mt < 4; mt++)
        #pragma unroll
        for (int nt = 0; nt < 4; nt++)
            #pragma unroll
            for (int i = 0; i < 4; i++) acc[mt][nt][i] = 0.f;

    for (int kt = 0; kt < K; kt += 32) {
        // Stage A
        if (A_BF16) {
            const __nv_bfloat16* A = (const __nv_bfloat16*)Ap;
            #pragma unroll
            for (int i = 0; i < 2; i++) {
                int idx = tid + i * 256;
                int r = idx >> 2, c = (idx & 3) * 8;
                const __nv_bfloat16* src = A + (size_t)(bm * 128 + r) * K + kt + c;
                *reinterpret_cast<uint4*>(&As[r][c]) = *reinterpret_cast<const uint4*>(src);
            }
        } else {
            const float* A = (const float*)Ap;
            #pragma unroll
            for (int i = 0; i < 4; i++) {
                int idx = tid + i * 256;
                int r = idx >> 3, c = (idx & 7) * 4;
                float4 v = *reinterpret_cast<const float4*>(A + (size_t)(bm * 128 + r) * K + kt + c);
                *reinterpret_cast<__nv_bfloat162*>(&As[r][c])     = __floats2bfloat162_rn(v.x, v.y);
                *reinterpret_cast<__nv_bfloat162*>(&As[r][c + 2]) = __floats2bfloat162_rn(v.z, v.w);
            }
        }
        // Stage W transposed -> Bs[n][k]
        #pragma unroll
        for (int i = 0; i < 4; i++) {
            int idx = tid + i * 256;
            int r = idx >> 5, c = (idx & 31) * 4;
            float4 v = *reinterpret_cast<const float4*>(W + (size_t)(kt + r) * N + bn * 128 + c);
            Bs[c + 0][r] = __float2bfloat16_rn(v.x);
            Bs[c + 1][r] = __float2bfloat16_rn(v.y);
            Bs[c + 2][r] = __float2bfloat16_rn(v.z);
            Bs[c + 3][r] = __float2bfloat16_rn(v.w);
        }
        __syncthreads();

        #pragma unroll
        for (int kk = 0; kk < 32; kk += 16) {
            uint32_t aA[4][4];
            #pragma unroll
            for (int mt = 0; mt < 4; mt++) {
                int r = wm * 64 + mt * 16 + gid;
                aA[mt][0] = *reinterpret_cast<const uint32_t*>(&As[r][kk + 2 * tig]);
                aA[mt][1] = *reinterpret_cast<const uint32_t*>(&As[r + 8][kk + 2 * tig]);
                aA[mt][2] = *reinterpret_cast<const uint32_t*>(&As[r][kk + 2 * tig + 8]);
                aA[mt][3] = *reinterpret_cast<const uint32_t*>(&As[r + 8][kk + 2 * tig + 8]);
            }
            uint32_t bB[4][2];
            #pragma unroll
            for (int nt = 0; nt < 4; nt++) {
                int n = wn * 32 + nt * 8 + gid;
                bB[nt][0] = *reinterpret_cast<const uint32_t*>(&Bs[n][kk + 2 * tig]);
                bB[nt][1] = *reinterpret_cast<const uint32_t*>(&Bs[n][kk + 2 * tig + 8]);
            }
            #pragma unroll
            for (int mt = 0; mt < 4; mt++)
                #pragma unroll
                for (int nt = 0; nt < 4; nt++)
                    mma_bf16(acc[mt][nt], aA[mt], bB[nt]);
        }
        __syncthreads();
    }

    // Epilogue
    #pragma unroll
    for (int mt = 0; mt < 4; mt++) {
        int row = bm * 128 + wm * 64 + mt * 16 + gid;
        #pragma unroll
        for (int nt = 0; nt < 4; nt++) {
            int col = bn * 128 + wn * 32 + nt * 8 + 2 * tig;
            float b0 = bias[col], b1 = bias[col + 1];
            size_t i0 = (size_t)row * N + col;
            size_t i1 = i0 + 8 * (size_t)N;
            float v0 = acc[mt][nt][0] + b0, v1 = acc[mt][nt][1] + b1;
            float v2 = acc[mt][nt][2] + b0, v3 = acc[mt][nt][3] + b1;
            if (OUT_BF16) {
                __nv_bfloat16* C = (__nv_bfloat16*)Cp;
                *reinterpret_cast<__nv_bfloat162*>(C + i0) = __floats2bfloat162_rn(v0, v1);
                *reinterpret_cast<__nv_bfloat162*>(C + i1) = __floats2bfloat162_rn(v2, v3);
            } else {
                float* C = (float*)Cp;
                if (ADD_RES) { v0 += res[i0]; v1 += res[i0 + 1]; v2 += res[i1]; v3 += res[i1 + 1]; }
                C[i0] = v0; C[i0 + 1] = v1; C[i1] = v2; C[i1 + 1] = v3;
            }
        }
    }
}

// ---------------------------------------------------------------------------
// Flash attention over 2S keys, bf16 mma m16n8k16, P kept in registers
// (accumulator->A-fragment identity), V^T via ldmatrix.x4.trans.
// Block = (qtile 64 rows, head, bf). 4 warps.
// ---------------------------------------------------------------------------
__global__ __launch_bounds__(128)
void attn_kernel()
{
    __shared__ __nv_bfloat16 Qs[64][72];
    __shared__ __nv_bfloat16 Ks[64][72];
    __shared__ __nv_bfloat16 Vs[64][72];

    const int qt = blockIdx.x, h = blockIdx.y, bfi = blockIdx.z;
    const int bf0 = bfi & ~(N_FR - 1);
    const int tid = threadIdx.x;
    const int w = tid >> 5, lane = tid & 31;
    const int gid = lane >> 2, tig = lane & 3;

    // Stage Q tile, pre-scaled by 1/sqrt(64) = 0.125 (exact in bf16)
    {
        const __nv_bfloat162 sc = __floats2bfloat162_rn(0.125f, 0.125f);
        #pragma unroll
        for (int i = 0; i < 4; i++) {
            int idx = tid + i * 128;
            int r = idx >> 3, c = (idx & 7) * 8;
            const __nv_bfloat16* p = g_q + (size_t)(bfi * SEQ + qt * 64 + r) * D_MODEL + h * HDIM + c;
            uint4 v = *reinterpret_cast<const uint4*>(p);
            __nv_bfloat162* pv = reinterpret_cast<__nv_bfloat162*>(&v);
            #pragma unroll
            for (int j = 0; j < 4; j++) pv[j] = __hmul2(pv[j], sc);
            *reinterpret_cast<uint4*>(&Qs[r][c]) = v;
        }
    }
    __syncthreads();

    float oacc[8][4];
    #pragma unroll
    for (int nt = 0; nt < 8; nt++)
        #pragma unroll
        for (int i = 0; i < 4; i++) oacc[nt][i] = 0.f;
    float m0 = -3e38f, m1 = -3e38f, l0 = 0.f, l1 = 0.f;

    const int r0 = w * 16 + gid;    // first q row of this thread within tile

    for (int t = 0; t < 32; t++) {
        const int sbf = (t < 16) ? bf0 : bfi;
        const int k0 = (t & 15) * 64;

        #pragma unroll
        for (int i = 0; i < 4; i++) {
            int idx = tid + i * 128;
            int r = idx >> 3, c = (idx & 7) * 8;
            size_t base = (size_t)(sbf * SEQ + k0 + r) * D_MODEL + h * HDIM + c;
            *reinterpret_cast<uint4*>(&Ks[r][c]) = *reinterpret_cast<const uint4*>(g_k + base);
            *reinterpret_cast<uint4*>(&Vs[r][c]) = *reinterpret_cast<const uint4*>(g_v + base);
        }
        __syncthreads();

        // S = Q_scaled @ K^T : 16x64 per warp
        float sacc[8][4];
        #pragma unroll
        for (int nt = 0; nt < 8; nt++)
            #pragma unroll
            for (int i = 0; i < 4; i++) sacc[nt][i] = 0.f;

        #pragma unroll
        for (int kk = 0; kk < 64; kk += 16) {
            uint32_t aq[4];
            aq[0] = *reinterpret_cast<const uint32_t*>(&Qs[r0][kk + 2 * tig]);
            aq[1] = *reinterpret_cast<const uint32_t*>(&Qs[r0 + 8][kk + 2 * tig]);
            aq[2] = *reinterpret_cast<const uint32_t*>(&Qs[r0][kk + 2 * tig + 8]);
            aq[3] = *reinterpret_cast<const uint32_t*>(&Qs[r0 + 8][kk + 2 * tig + 8]);
            #pragma unroll
            for (int nt = 0; nt < 8; nt++) {
                uint32_t bk[2];
                bk[0] = *reinterpret_cast<const uint32_t*>(&Ks[nt * 8 + gid][kk + 2 * tig]);
                bk[1] = *reinterpret_cast<const uint32_t*>(&Ks[nt * 8 + gid][kk + 2 * tig + 8]);
                mma_bf16(sacc[nt], aq, bk);
            }
        }

        // Online softmax (rows r0, r0+8)
        float mx0 = -3e38f, mx1 = -3e38f;
        #pragma unroll
        for (int nt = 0; nt < 8; nt++) {
            mx0 = fmaxf(mx0, fmaxf(sacc[nt][0], sacc[nt][1]));
            mx1 = fmaxf(mx1, fmaxf(sacc[nt][2], sacc[nt][3]));
        }
        mx0 = fmaxf(mx0, __shfl_xor_sync(0xffffffffu, mx0, 1));
        mx0 = fmaxf(mx0, __shfl_xor_sync(0xffffffffu, mx0, 2));
        mx1 = fmaxf(mx1, __shfl_xor_sync(0xffffffffu, mx1, 1));
        mx1 = fmaxf(mx1, __shfl_xor_sync(0xffffffffu, mx1, 2));

        float mn0 = fmaxf(m0, mx0), mn1 = fmaxf(m1, mx1);
        float a0 = __expf(m0 - mn0), a1 = __expf(m1 - mn1);
        float s0 = 0.f, s1 = 0.f;
        #pragma unroll
        for (int nt = 0; nt < 8; nt++) {
            float p0 = __expf(sacc[nt][0] - mn0), p1 = __expf(sacc[nt][1] - mn0);
            float p2 = __expf(sacc[nt][2] - mn1), p3 = __expf(sacc[nt][3] - mn1);
            s0 += p0 + p1; s1 += p2 + p3;
            sacc[nt][0] = p0; sacc[nt][1] = p1; sacc[nt][2] = p2; sacc[nt][3] = p3;
        }
        s0 += __shfl_xor_sync(0xffffffffu, s0, 1);
        s0 += __shfl_xor_sync(0xffffffffu, s0, 2);
        s1 += __shfl_xor_sync(0xffffffffu, s1, 1);
        s1 += __shfl_xor_sync(0xffffffffu, s1, 2);
        l0 = l0 * a0 + s0; l1 = l1 * a1 + s1;
        m0 = mn0; m1 = mn1;

        #pragma unroll
        for (int nt = 0; nt < 8; nt++) {
            oacc[nt][0] *= a0; oacc[nt][1] *= a0;
            oacc[nt][2] *= a1; oacc[nt][3] *= a1;
        }

        // O += P @ V : P from registers (acc->A-frag identity), V^T via ldmatrix.trans
        #pragma unroll
        for (int kj = 0; kj < 4; kj++) {
            uint32_t ap[4];
            ap[0] = packbf(sacc[2 * kj][0],     sacc[2 * kj][1]);
            ap[1] = packbf(sacc[2 * kj][2],     sacc[2 * kj][3]);
            ap[2] = packbf(sacc[2 * kj + 1][0], sacc[2 * kj + 1][1]);
            ap[3] = packbf(sacc[2 * kj + 1][2], sacc[2 * kj + 1][3]);
            #pragma unroll
            for (int dp = 0; dp < 4; dp++) {
                int vrow = kj * 16 + ((lane >> 3) & 1) * 8 + (lane & 7);
                int vcol = dp * 16 + ((lane >> 4) & 1) * 8;
                uint32_t addr = (uint32_t)__cvta_generic_to_shared(&Vs[vrow][vcol]);
                uint32_t b0, b1, b2, b3;
                asm volatile(
                    "ldmatrix.sync.aligned.m8n8.x4.trans.shared.b16 {%0,%1,%2,%3}, [%4];\n"
                    : "=r"(b0), "=r"(b1), "=r"(b2), "=r"(b3) : "r"(addr));
                uint32_t bb0[2] = {b0, b1};
                uint32_t bb1[2] = {b2, b3};
                mma_bf16(oacc[2 * dp],     ap, bb0);
                mma_bf16(oacc[2 * dp + 1], ap, bb1);
            }
        }
        __syncthreads();
    }

    const float inv0 = 1.f / l0, inv1 = 1.f / l1;
    #pragma unroll
    for (int nt = 0; nt < 8; nt++) {
        int dcol = h * HDIM + nt * 8 + 2 * tig;
        size_t b0 = (size_t)(bfi * SEQ + qt * 64 + r0) * D_MODEL + dcol;
        size_t b1 = b0 + 8 * (size_t)D_MODEL;
        *reinterpret_cast<__nv_bfloat162*>(g_attn + b0) =
            __floats2bfloat162_rn(oacc[nt][0] * inv0, oacc[nt][1] * inv0);
        *reinterpret_cast<__nv_bfloat162*>(g_attn + b1) =
            __floats2bfloat162_rn(oacc[nt][2] * inv1, oacc[nt][3] * inv1);
    }
}

// ---------------------------------------------------------------------------

extern "C" void kernel_launch(void* const* d_in, const int* in_sizes, int n_in,
                              void* d_out, int out_size)
{
    const float* hs = (const float*)d_in[0];
    const float* Wq = (const float*)d_in[1];
    const float* Wk = (const float*)d_in[2];
    const float* Wv = (const float*)d_in[3];
    const float* Wo = (const float*)d_in[4];
    const float* bq = (const float*)d_in[5];
    const float* bk = (const float*)d_in[6];
    const float* bv = (const float*)d_in[7];
    const float* bo = (const float*)d_in[8];
    float* out = (float*)d_out;

    void *qp, *kp, *vp, *ap;
    cudaGetSymbolAddress(&qp, g_q);
    cudaGetSymbolAddress(&kp, g_k);
    cudaGetSymbolAddress(&vp, g_v);
    cudaGetSymbolAddress(&ap, g_attn);

    dim3 blk(256), grd(D_MODEL / 128, M_TOT / 128);
    gemm_kernel<false, true, false><<<grd, blk>>>(hs, Wq, bq, nullptr, qp, M_TOT, D_MODEL, D_MODEL);
    gemm_kernel<false, true, false><<<grd, blk>>>(hs, Wk, bk, nullptr, kp, M_TOT, D_MODEL, D_MODEL);
    gemm_kernel<false, true, false><<<grd, blk>>>(hs, Wv, bv, nullptr, vp, M_TOT, D_MODEL, D_MODEL);

    attn_kernel<<<dim3(SEQ / 64, N_HEADS, N_BF), 128>>>();

    gemm_kernel<true, false, true><<<grd, blk>>>(ap, Wo, bo, hs, out, M_TOT, D_MODEL, D_MODEL);
}